// round 3
// baseline (speedup 1.0000x reference)
#include <cuda_runtime.h>

// Problem constants (from reference: pred_softmax (16, 11, 1, 512, 512) fp32)
#define BDIM   16
#define PDIM   11
#define PM1    10          // parts used (drop last)
#define HDIM   512
#define WDIM   512
#define NMAPS  (BDIM * PM1)        // 160
#define CHUNKS 8                   // chunks per map
#define NBLK   (NMAPS * CHUNKS)    // 1280 blocks
#define THREADS 256
#define ROWS_PER_CHUNK (HDIM / CHUNKS)              // 64 rows
#define F4_PER_CHUNK   (ROWS_PER_CHUNK * WDIM / 4)  // 8192 float4 per chunk
#define F4_PER_ROW     (WDIM / 4)                   // 128

// Deterministic scratch for block partials: [block][5] = {S, Sx, Sy, Sxx, Syy}
__device__ float g_part[NBLK * 5];

__global__ void __launch_bounds__(THREADS)
moments_stage1(const float* __restrict__ in)
{
    const int blk   = blockIdx.x;
    const int map   = blk / CHUNKS;        // 0..159
    const int chunk = blk % CHUNKS;        // 0..7
    const int b = map / PM1;
    const int p = map % PM1;

    // flat offset of this map (skips part index PM1..P-1 naturally)
    const size_t map_off = (size_t)(b * PDIM + p) * (size_t)(HDIM * WDIM);
    const float4* __restrict__ src =
        (const float4*)(in + map_off + (size_t)chunk * ROWS_PER_CHUNK * WDIM);

    const float c = 2.0f / (float)WDIM;    // 1/256: coord step
    const int tid = threadIdx.x;

    float S = 0.f, Sx = 0.f, Sy = 0.f, Sxx = 0.f, Syy = 0.f;

    #pragma unroll 4
    for (int i = tid; i < F4_PER_CHUNK; i += THREADS) {
        float4 v = src[i];

        const int   hl = i >> 7;                           // local row (128 f4/row)
        const float ym = (float)(chunk * ROWS_PER_CHUNK + hl) * c - 1.0f;
        const float xm = (float)((i & 127) * 4) * c - 1.0f;

        const float s4 = (v.x + v.y) + (v.z + v.w);
        S += s4;
        const float t = s4 * ym;
        Sy  += t;
        Syy  = fmaf(t, ym, Syy);

        const float x0 = xm;
        const float x1 = xm + c;
        const float x2 = xm + 2.0f * c;
        const float x3 = xm + 3.0f * c;
        Sx  = fmaf(v.x, x0, Sx);  Sxx = fmaf(v.x * x0, x0, Sxx);
        Sx  = fmaf(v.y, x1, Sx);  Sxx = fmaf(v.y * x1, x1, Sxx);
        Sx  = fmaf(v.z, x2, Sx);  Sxx = fmaf(v.z * x2, x2, Sxx);
        Sx  = fmaf(v.w, x3, Sx);  Sxx = fmaf(v.w * x3, x3, Sxx);
    }

    // warp reduce (fixed order -> deterministic)
    #pragma unroll
    for (int o = 16; o; o >>= 1) {
        S   += __shfl_xor_sync(0xffffffffu, S,   o);
        Sx  += __shfl_xor_sync(0xffffffffu, Sx,  o);
        Sy  += __shfl_xor_sync(0xffffffffu, Sy,  o);
        Sxx += __shfl_xor_sync(0xffffffffu, Sxx, o);
        Syy += __shfl_xor_sync(0xffffffffu, Syy, o);
    }

    __shared__ float sm[THREADS / 32][5];
    const int wid = tid >> 5, lid = tid & 31;
    if (lid == 0) {
        sm[wid][0] = S; sm[wid][1] = Sx; sm[wid][2] = Sy;
        sm[wid][3] = Sxx; sm[wid][4] = Syy;
    }
    __syncthreads();

    if (tid < 5) {
        float acc = 0.f;
        #pragma unroll
        for (int w = 0; w < THREADS / 32; w++) acc += sm[w][tid];
        g_part[blk * 5 + tid] = acc;
    }
}

__global__ void __launch_bounds__(256)
moments_stage2(float* __restrict__ out)
{
    const int tid = threadIdx.x;
    float v = 0.f;

    if (tid < NMAPS) {
        float a0 = 0.f, a1 = 0.f, a2 = 0.f, a3 = 0.f, a4 = 0.f;
        #pragma unroll
        for (int cch = 0; cch < CHUNKS; cch++) {
            const int base = (tid * CHUNKS + cch) * 5;
            a0 += g_part[base + 0];
            a1 += g_part[base + 1];
            a2 += g_part[base + 2];
            a3 += g_part[base + 3];
            a4 += g_part[base + 4];
        }
        const float k   = a0 + 1e-8f;
        const float inv = 1.0f / k;
        const float xc  = a1 * inv;
        const float yc  = a2 * inv;
        // exact expansion of sum(pdf * (map - centroid)^2), incl. sum(pdf)!=1
        const float vx = (a3 - 2.0f * xc * a1 + xc * xc * a0) * inv;
        const float vy = (a4 - 2.0f * yc * a2 + yc * yc * a0) * inv;
        v = vx + vy;
    }

    #pragma unroll
    for (int o = 16; o; o >>= 1) v += __shfl_xor_sync(0xffffffffu, v, o);

    __shared__ float sm[8];
    if ((tid & 31) == 0) sm[tid >> 5] = v;
    __syncthreads();

    if (tid == 0) {
        float t = 0.f;
        #pragma unroll
        for (int i = 0; i < 8; i++) t += sm[i];
        out[0] = t / (float)BDIM;
    }
}

extern "C" void kernel_launch(void* const* d_in, const int* in_sizes, int n_in,
                              void* d_out, int out_size)
{
    const float* pred = (const float*)d_in[0];
    float* out = (float*)d_out;
    (void)in_sizes; (void)n_in; (void)out_size;

    moments_stage1<<<NBLK, THREADS>>>(pred);
    moments_stage2<<<1, 256>>>(out);
}

// round 4
// speedup vs baseline: 1.1721x; 1.1721x over previous
#include <cuda_runtime.h>

// Problem constants (pred_softmax: (16, 11, 1, 512, 512) fp32)
#define BDIM   16
#define PDIM   11
#define PM1    10
#define HDIM   512
#define WDIM   512
#define NMAPS  (BDIM * PM1)        // 160
#define CHUNKS 8
#define NBLK   (NMAPS * CHUNKS)    // 1280
#define THREADS 256
#define ROWS_PER_CHUNK (HDIM / CHUNKS)              // 64
#define F4_PER_CHUNK   (ROWS_PER_CHUNK * WDIM / 4)  // 8192
#define ITERS  (F4_PER_CHUNK / THREADS)             // 32
#define UNROLL 8

// Deterministic scratch: [block][5] = {S, Sx, Sy, Sxx, Syy}
__device__ float g_part[NBLK * 5];
__device__ unsigned int g_count;   // zero-init at load; reset by last block

__global__ void __launch_bounds__(THREADS)
moments_fused(const float* __restrict__ in, float* __restrict__ out)
{
    const int blk   = blockIdx.x;
    const int map   = blk / CHUNKS;
    const int chunk = blk % CHUNKS;
    const int b = map / PM1;
    const int p = map % PM1;

    const size_t map_off = (size_t)(b * PDIM + p) * (size_t)(HDIM * WDIM);
    const float4* __restrict__ src =
        (const float4*)(in + map_off + (size_t)chunk * ROWS_PER_CHUNK * WDIM);

    const float c = 2.0f / (float)WDIM;   // 1/256
    const int tid = threadIdx.x;

    float S = 0.f, Sx = 0.f, Sy = 0.f, Sxx = 0.f, Syy = 0.f;

    #pragma unroll
    for (int j = 0; j < ITERS; j += UNROLL) {
        // front-batch UNROLL independent 128-bit streaming loads (MLP=8)
        float4 v[UNROLL];
        #pragma unroll
        for (int u = 0; u < UNROLL; u++)
            v[u] = __ldcs(&src[tid + (j + u) * THREADS]);

        #pragma unroll
        for (int u = 0; u < UNROLL; u++) {
            const int i = tid + (j + u) * THREADS;
            const int   hl = i >> 7;                        // 128 f4 per row
            const float ym = (float)(chunk * ROWS_PER_CHUNK + hl) * c - 1.0f;
            const float xm = (float)((i & 127) * 4) * c - 1.0f;

            const float s4 = (v[u].x + v[u].y) + (v[u].z + v[u].w);
            S += s4;
            const float t = s4 * ym;
            Sy  += t;
            Syy  = fmaf(t, ym, Syy);

            const float x0 = xm;
            const float x1 = xm + c;
            const float x2 = xm + 2.0f * c;
            const float x3 = xm + 3.0f * c;
            Sx = fmaf(v[u].x, x0, Sx);  Sxx = fmaf(v[u].x * x0, x0, Sxx);
            Sx = fmaf(v[u].y, x1, Sx);  Sxx = fmaf(v[u].y * x1, x1, Sxx);
            Sx = fmaf(v[u].z, x2, Sx);  Sxx = fmaf(v[u].z * x2, x2, Sxx);
            Sx = fmaf(v[u].w, x3, Sx);  Sxx = fmaf(v[u].w * x3, x3, Sxx);
        }
    }

    // warp reduce (fixed order)
    #pragma unroll
    for (int o = 16; o; o >>= 1) {
        S   += __shfl_xor_sync(0xffffffffu, S,   o);
        Sx  += __shfl_xor_sync(0xffffffffu, Sx,  o);
        Sy  += __shfl_xor_sync(0xffffffffu, Sy,  o);
        Sxx += __shfl_xor_sync(0xffffffffu, Sxx, o);
        Syy += __shfl_xor_sync(0xffffffffu, Syy, o);
    }

    __shared__ float sm[THREADS / 32][5];
    const int wid = tid >> 5, lid = tid & 31;
    if (lid == 0) {
        sm[wid][0] = S; sm[wid][1] = Sx; sm[wid][2] = Sy;
        sm[wid][3] = Sxx; sm[wid][4] = Syy;
    }
    __syncthreads();

    if (tid < 5) {
        float acc = 0.f;
        #pragma unroll
        for (int w = 0; w < THREADS / 32; w++) acc += sm[w][tid];
        g_part[blk * 5 + tid] = acc;
    }

    // ---- last-block final reduction (replaces tail kernel) ----
    __threadfence();
    __shared__ unsigned int s_ticket;
    if (tid == 0) s_ticket = atomicAdd(&g_count, 1u);
    __syncthreads();
    if (s_ticket != NBLK - 1) return;

    if (tid == 0) g_count = 0;   // reset for next graph replay (deterministic)

    float v = 0.f;
    if (tid < NMAPS) {
        float a0 = 0.f, a1 = 0.f, a2 = 0.f, a3 = 0.f, a4 = 0.f;
        #pragma unroll
        for (int cch = 0; cch < CHUNKS; cch++) {
            const int base = (tid * CHUNKS + cch) * 5;
            a0 += g_part[base + 0];
            a1 += g_part[base + 1];
            a2 += g_part[base + 2];
            a3 += g_part[base + 3];
            a4 += g_part[base + 4];
        }
        const float k   = a0 + 1e-8f;
        const float inv = 1.0f / k;
        const float xc  = a1 * inv;
        const float yc  = a2 * inv;
        const float vx = (a3 - 2.0f * xc * a1 + xc * xc * a0) * inv;
        const float vy = (a4 - 2.0f * yc * a2 + yc * yc * a0) * inv;
        v = vx + vy;
    }

    #pragma unroll
    for (int o = 16; o; o >>= 1) v += __shfl_xor_sync(0xffffffffu, v, o);

    __shared__ float sm2[THREADS / 32];
    if ((tid & 31) == 0) sm2[tid >> 5] = v;
    __syncthreads();

    if (tid == 0) {
        float t = 0.f;
        #pragma unroll
        for (int i = 0; i < THREADS / 32; i++) t += sm2[i];
        out[0] = t / (float)BDIM;
    }
}

extern "C" void kernel_launch(void* const* d_in, const int* in_sizes, int n_in,
                              void* d_out, int out_size)
{
    const float* pred = (const float*)d_in[0];
    float* out = (float*)d_out;
    (void)in_sizes; (void)n_in; (void)out_size;

    moments_fused<<<NBLK, THREADS>>>(pred, out);
}